// round 6
// baseline (speedup 1.0000x reference)
#include <cuda_runtime.h>
#include <cstddef>
#include <cstdint>

#define NF 1025
#define NM 128
#define NB 4
#define TT 1024
#define ROWS 4
#define NTHREADS 256
#define ITERS 20
#define NBLOCKS ((NB * TT) / ROWS)   // 1024
#define NGR 256
#define NDIFF 131
#define DUMMYIDX 1024                // zero slot in s_p

typedef unsigned long long u64;

#define F2FMA(d,a,b,c) asm("fma.rn.f32x2 %0, %1, %2, %3;" : "=l"(d) : "l"(a), "l"(b), "l"(c))
#define F2MUL(d,a,b)   asm("mul.rn.f32x2 %0, %1, %2;"     : "=l"(d) : "l"(a), "l"(b))
#define F2ADD(d,a,b)   asm("add.rn.f32x2 %0, %1, %2;"     : "=l"(d) : "l"(a), "l"(b))
#define PK2(d,lo,hi)   asm("mov.b64 %0, {%1, %2};" : "=l"(d) : "f"(lo), "f"(hi))
#define UPK2(lo,hi,s)  asm("mov.b64 {%0, %1}, %2;" : "=f"(lo), "=f"(hi) : "l"(s))

__device__ float  g_w0[NF];
__device__ float  g_w1[NF];
__device__ int    g_mi[NF];
__device__ float4 g_wv[NGR * 4];
__device__ int    g_mb[NGR];
__device__ unsigned g_sinfo[NTHREADS];          // leader: mel | cc<<16 ; else 0xFFFF
__device__ unsigned short g_slist[NTHREADS * 8];// 8 term indices per slot (chunk)

// ---------------------------------------------------------------------------
// Prep 1: warp per frequency row. One coalesced float4 load per lane,
// warp-min for first nonzero mel, shfl to fetch the two weights.
// ---------------------------------------------------------------------------
__global__ void prep_freq(const float* __restrict__ fb) {
    int gw   = (blockIdx.x * blockDim.x + threadIdx.x) >> 5;
    int lane = threadIdx.x & 31;
    if (gw >= NF) return;
    const float4 v = ((const float4*)(fb + (size_t)gw * NM))[lane];
    int cand = 128;
    if (v.w > 0.0f) cand = lane * 4 + 3;
    if (v.z > 0.0f) cand = lane * 4 + 2;
    if (v.y > 0.0f) cand = lane * 4 + 1;
    if (v.x > 0.0f) cand = lane * 4;
#pragma unroll
    for (int o = 16; o; o >>= 1) {
        int other = __shfl_xor_sync(0xFFFFFFFFu, cand, o);
        cand = (other < cand) ? other : cand;
    }
    int mi = cand;
    float w0 = 0.0f, w1 = 0.0f;
    if (mi < 128) {
        int e0 = mi & 3;
        float my0 = (e0 == 0) ? v.x : (e0 == 1) ? v.y : (e0 == 2) ? v.z : v.w;
        w0 = __shfl_sync(0xFFFFFFFFu, my0, mi >> 2);
        int m1 = mi + 1;
        if (m1 < 128) {
            int e1 = m1 & 3;
            float my1 = (e1 == 0) ? v.x : (e1 == 1) ? v.y : (e1 == 2) ? v.z : v.w;
            w1 = __shfl_sync(0xFFFFFFFFu, my1, m1 >> 2);
        }
    } else mi = 0;
    if (lane == 0) { g_mi[gw] = mi; g_w0[gw] = w0; g_w1[gw] = w1; }
}

// ---------------------------------------------------------------------------
// Prep 2 (single block): granule weight blocks + chunked, warp-contained
// reduction schedule (<=3 chunks of 8 terms per mel; one chunk per lane).
// ---------------------------------------------------------------------------
__global__ void prep_sched() {
    __shared__ int s_mb[NGR];
    __shared__ unsigned char s_nzm[NGR];
    __shared__ int s_cnt[NM], s_start[NM], s_ccs[NM];
    const int t = threadIdx.x;

    {   // per-granule 4-channel weights
        const int g = t;
        const int mb = g_mi[4 * g];
        float wv[4][4];
#pragma unroll
        for (int c = 0; c < 4; c++)
#pragma unroll
            for (int e = 0; e < 4; e++) wv[c][e] = 0.0f;
#pragma unroll
        for (int e = 0; e < 4; e++) {
            int f = 4 * g + e;
            int c0 = g_mi[f] - mb;
            if (c0 < 0) c0 = 0;
            if (c0 > 2) c0 = 2;
            wv[c0][e]     += g_w0[f];
            wv[c0 + 1][e] += g_w1[f];
        }
        unsigned char nz = 0;
#pragma unroll
        for (int c = 0; c < 4; c++) {
            float4 v = make_float4(wv[c][0], wv[c][1], wv[c][2], wv[c][3]);
            g_wv[g * 4 + c] = v;
            if (v.x != 0.0f || v.y != 0.0f || v.z != 0.0f || v.w != 0.0f)
                nz |= (unsigned char)(1u << c);
        }
        s_mb[g] = mb;
        s_nzm[g] = nz;
        g_mb[g] = mb;
    }
    __syncthreads();

    if (t < NM) {       // term count per mel
        int n = 0;
        for (int g = 0; g < NGR; g++) {
            int c = t - s_mb[g];
            if (c >= 0 && c < 4 && ((s_nzm[g] >> c) & 1)) n++;
        }
        s_cnt[t] = n;
    }
    __syncthreads();

    if (t == 0) {       // slot allocation, warp-contained per mel
        int slot = 0;
        for (int m = 0; m < NM; m++) {
            int cc = (s_cnt[m] + 7) >> 3;
            if (cc < 1) cc = 1;
            if (cc > 3) cc = 3;              // analysis: cnt <= ~14 -> cc <= 2
            if ((slot & 31) + cc > 32) slot = (slot + 31) & ~31;
            s_start[m] = slot; s_ccs[m] = cc; slot += cc;
        }
    }
    __syncthreads();

    // defaults: non-leader, all-dummy chunks
    g_sinfo[t] = 0xFFFFu;
#pragma unroll
    for (int j = 0; j < 8; j++) g_slist[t * 8 + j] = (unsigned short)DUMMYIDX;
    __syncthreads();

    if (t < NM) {       // emit per-mel chunk lists + leader info
        int st = s_start[t], cc = s_ccs[t];
        g_sinfo[st] = (unsigned)t | ((unsigned)cc << 16);
        int n = 0;
        for (int g = 0; g < NGR; g++) {
            int c = t - s_mb[g];
            if (c >= 0 && c < 4 && ((s_nzm[g] >> c) & 1)) {
                if (n < cc * 8) g_slist[st * 8 + n] = (unsigned short)(c * NGR + g);
                n++;
            }
        }
    }
}

// ---------------------------------------------------------------------------
// Main: 20 SGD iterations, 4 rows/CTA, packed f32x2 state, occupancy 4.
// ---------------------------------------------------------------------------
__global__ __launch_bounds__(NTHREADS, 4)
void invmel_main(const float* __restrict__ melspec,
                 const float* __restrict__ spec_init,
                 float* __restrict__ out) {
    __shared__ float4 s_p[4 * NGR + 1];   // + zero dummy slot
    __shared__ float4 s_diff[NDIFF];
    __shared__ uint4  s_slist[NTHREADS];

    const float cINV = 2.0f / (float)(NB * TT);
    const int tid  = threadIdx.x;
    const int row0 = blockIdx.x * ROWS;
    const int b    = row0 / TT;
    const int t0   = row0 % TT;

    // scalar weights (16 regs); pairs built on the fly
    float wv[4][4];
#pragma unroll
    for (int c = 0; c < 4; c++) {
        float4 v = g_wv[tid * 4 + c];
        wv[c][0] = v.x; wv[c][1] = v.y; wv[c][2] = v.z; wv[c][3] = v.w;
    }
    const int mb = g_mb[tid];

    // packed state
    u64 sp01[4], sp23[4], rb01[4], rb23[4];
#pragma unroll
    for (int e = 0; e < 4; e++) {
        float v0 = spec_init[(size_t)(row0 + 0) * NF + 4 * tid + e];
        float v1 = spec_init[(size_t)(row0 + 1) * NF + 4 * tid + e];
        float v2 = spec_init[(size_t)(row0 + 2) * NF + 4 * tid + e];
        float v3 = spec_init[(size_t)(row0 + 3) * NF + 4 * tid + e];
        PK2(sp01[e], v0, v1);
        PK2(sp23[e], v2, v3);
        rb01[e] = 0ull; rb23[e] = 0ull;
    }
    u64 kMOM, kNINV, kNLR;
    PK2(kMOM, 0.9f, 0.9f);
    PK2(kNINV, -cINV, -cINV);
    PK2(kNLR, -0.3f, -0.3f);

    // reduction slot identity
    const unsigned sinfo = g_sinfo[tid];
    const int lmel = (int)(sinfo & 0xFFFFu);
    const int lcc  = (int)(sinfo >> 16);
    const float4* melp = (lmel < NM)
        ? (const float4*)&melspec[((size_t)b * NM + lmel) * TT + t0]
        : (const float4*)melspec;

    s_slist[tid] = ((const uint4*)g_slist)[tid];
    if (tid == 0) s_p[4 * NGR] = make_float4(0.f, 0.f, 0.f, 0.f);
    if (tid < NDIFF - NM) s_diff[NM + tid] = make_float4(0.f, 0.f, 0.f, 0.f);
    __syncthreads();

    for (int it = 0; it < ITERS; it++) {
        // ---- P1: per-granule channel partials (packed) ----
#pragma unroll
        for (int c = 0; c < 4; c++) {
            u64 wp, a01, a23;
            PK2(wp, wv[c][0], wv[c][0]);
            F2MUL(a01, wp, sp01[0]);
            F2MUL(a23, wp, sp23[0]);
#pragma unroll
            for (int e = 1; e < 4; e++) {
                PK2(wp, wv[c][e], wv[c][e]);
                F2FMA(a01, wp, sp01[e], a01);
                F2FMA(a23, wp, sp23[e], a23);
            }
            ulonglong2 stv; stv.x = a01; stv.y = a23;
            *(ulonglong2*)&s_p[c * NGR + tid] = stv;
        }
        __syncthreads();

        // ---- Stage A: uniform 8-term chunk sum (pairwise tree) ----
        const uint4 L = s_slist[tid];
        const int i0 = L.x & 0xFFFF, i1 = L.x >> 16;
        const int i2 = L.y & 0xFFFF, i3 = L.y >> 16;
        const int i4 = L.z & 0xFFFF, i5 = L.z >> 16;
        const int i6 = L.w & 0xFFFF, i7 = L.w >> 16;
        ulonglong2 v0 = *(const ulonglong2*)&s_p[i0];
        ulonglong2 v1 = *(const ulonglong2*)&s_p[i1];
        ulonglong2 v2 = *(const ulonglong2*)&s_p[i2];
        ulonglong2 v3 = *(const ulonglong2*)&s_p[i3];
        ulonglong2 v4 = *(const ulonglong2*)&s_p[i4];
        ulonglong2 v5 = *(const ulonglong2*)&s_p[i5];
        ulonglong2 v6 = *(const ulonglong2*)&s_p[i6];
        ulonglong2 v7 = *(const ulonglong2*)&s_p[i7];
        u64 a01, b01, c01, d01, a23, b23, c23, d23;
        F2ADD(a01, v0.x, v1.x); F2ADD(b01, v2.x, v3.x);
        F2ADD(c01, v4.x, v5.x); F2ADD(d01, v6.x, v7.x);
        F2ADD(a01, a01, b01);   F2ADD(c01, c01, d01);
        F2ADD(a01, a01, c01);
        F2ADD(a23, v0.y, v1.y); F2ADD(b23, v2.y, v3.y);
        F2ADD(c23, v4.y, v5.y); F2ADD(d23, v6.y, v7.y);
        F2ADD(a23, a23, b23);   F2ADD(c23, c23, d23);
        F2ADD(a23, a23, c23);

        // combine chunk partials of this mel (consecutive lanes, warp-contained)
        u64 s1a = __shfl_down_sync(0xFFFFFFFFu, a01, 1);
        u64 s1b = __shfl_down_sync(0xFFFFFFFFu, a23, 1);
        u64 s2a = __shfl_down_sync(0xFFFFFFFFu, a01, 2);
        u64 s2b = __shfl_down_sync(0xFFFFFFFFu, a23, 2);
        if (lmel < NM) {
            u64 t01 = a01, t23 = a23;
            if (lcc >= 2) { F2ADD(t01, t01, s1a); F2ADD(t23, t23, s1b); }
            if (lcc >= 3) { F2ADD(t01, t01, s2a); F2ADD(t23, t23, s2b); }
            float e0, e1, e2, e3;
            UPK2(e0, e1, t01);
            UPK2(e2, e3, t23);
            float4 mv = __ldg(melp);
            s_diff[lmel] = make_float4(mv.x - e0, mv.y - e1, mv.z - e2, mv.w - e3);
        }
        __syncthreads();

        // ---- P3: grad + momentum + clamp (packed) ----
        ulonglong2 d0 = *(const ulonglong2*)&s_diff[mb + 0];
        ulonglong2 d1 = *(const ulonglong2*)&s_diff[mb + 1];
        ulonglong2 d2 = *(const ulonglong2*)&s_diff[mb + 2];
        ulonglong2 d3 = *(const ulonglong2*)&s_diff[mb + 3];
#pragma unroll
        for (int e = 0; e < 4; e++) {
            u64 wp, g01, g23;
            PK2(wp, wv[0][e], wv[0][e]);
            F2MUL(g01, wp, d0.x);
            F2MUL(g23, wp, d0.y);
            PK2(wp, wv[1][e], wv[1][e]);
            F2FMA(g01, wp, d1.x, g01);
            F2FMA(g23, wp, d1.y, g23);
            PK2(wp, wv[2][e], wv[2][e]);
            F2FMA(g01, wp, d2.x, g01);
            F2FMA(g23, wp, d2.y, g23);
            PK2(wp, wv[3][e], wv[3][e]);
            F2FMA(g01, wp, d3.x, g01);
            F2FMA(g23, wp, d3.y, g23);
            u64 t01, t23;
            F2MUL(t01, kNINV, g01);
            F2MUL(t23, kNINV, g23);
            F2FMA(rb01[e], kMOM, rb01[e], t01);
            F2FMA(rb23[e], kMOM, rb23[e], t23);
            u64 s01, s23;
            F2FMA(s01, kNLR, rb01[e], sp01[e]);
            F2FMA(s23, kNLR, rb23[e], sp23[e]);
            float lo, hi;
            UPK2(lo, hi, s01);
            PK2(sp01[e], fmaxf(lo, 0.0f), fmaxf(hi, 0.0f));
            UPK2(lo, hi, s23);
            PK2(sp23[e], fmaxf(lo, 0.0f), fmaxf(hi, 0.0f));
        }
        // no barrier: next P1 rewrites s_p (read before last barrier);
        // s_diff rewritten only after the next iteration's first barrier.
    }

    // ---- output ----
#pragma unroll
    for (int e = 0; e < 4; e++) {
        ulonglong2 v; v.x = sp01[e]; v.y = sp23[e];
        *(ulonglong2*)&out[((size_t)b * NF + 4 * tid + e) * TT + t0] = v;
    }
    if (tid < ROWS) {   // f = 1024: zero fb row -> passthrough
        out[((size_t)b * NF + 1024) * TT + t0 + tid] =
            spec_init[(size_t)(row0 + tid) * NF + 1024];
    }
}

// ---------------------------------------------------------------------------
extern "C" void kernel_launch(void* const* d_in, const int* in_sizes, int n_in,
                              void* d_out, int out_size) {
    const float* melspec = nullptr;
    const float* spec_init = nullptr;
    const float* fb = nullptr;
    for (int i = 0; i < n_in; i++) {
        if (in_sizes[i] == NB * NM * TT)      melspec   = (const float*)d_in[i];
        else if (in_sizes[i] == NB * TT * NF) spec_init = (const float*)d_in[i];
        else if (in_sizes[i] == NF * NM)      fb        = (const float*)d_in[i];
    }
    float* out = (float*)d_out;

    prep_freq<<<(NF * 32 + 255) / 256, 256>>>(fb);
    prep_sched<<<1, NTHREADS>>>();
    invmel_main<<<NBLOCKS, NTHREADS>>>(melspec, spec_init, out);
}

// round 7
// speedup vs baseline: 1.0394x; 1.0394x over previous
#include <cuda_runtime.h>
#include <cstddef>
#include <cstdint>

#define NF 1025
#define NM 128
#define NB 4
#define TT 1024
#define ROWS 8
#define NTHREADS 256
#define ITERS 20
#define NBLOCKS ((NB * TT) / ROWS)   // 512
#define NGR 256
#define NDIFF 131
#define DUMMYIDX 1024                // zero slot in s_p planes

typedef unsigned long long u64;

#define F2FMA(d,a,b,c) asm("fma.rn.f32x2 %0, %1, %2, %3;" : "=l"(d) : "l"(a), "l"(b), "l"(c))
#define F2MUL(d,a,b)   asm("mul.rn.f32x2 %0, %1, %2;"     : "=l"(d) : "l"(a), "l"(b))
#define F2ADD(d,a,b)   asm("add.rn.f32x2 %0, %1, %2;"     : "=l"(d) : "l"(a), "l"(b))
#define PK2(d,lo,hi)   asm("mov.b64 %0, {%1, %2};" : "=l"(d) : "f"(lo), "f"(hi))
#define UPK2(lo,hi,s)  asm("mov.b64 {%0, %1}, %2;" : "=f"(lo), "=f"(hi) : "l"(s))

__device__ float  g_w0[NF];
__device__ float  g_w1[NF];
__device__ int    g_mi[NF];
__device__ float4 g_wv[NGR * 4];
__device__ int    g_mb[NGR];
__device__ unsigned g_sinfo[NTHREADS];           // leader: mel | cc<<16 ; else 0xFFFF
__device__ unsigned short g_slist[NTHREADS * 8]; // 8 term indices per slot (chunk)

// ---------------------------------------------------------------------------
// Prep 1: warp per frequency row; coalesced float4 + warp-min + shfl weights.
// ---------------------------------------------------------------------------
__global__ void prep_freq(const float* __restrict__ fb) {
    int gw   = (blockIdx.x * blockDim.x + threadIdx.x) >> 5;
    int lane = threadIdx.x & 31;
    if (gw >= NF) return;
    const float4 v = ((const float4*)(fb + (size_t)gw * NM))[lane];
    int cand = 128;
    if (v.w > 0.0f) cand = lane * 4 + 3;
    if (v.z > 0.0f) cand = lane * 4 + 2;
    if (v.y > 0.0f) cand = lane * 4 + 1;
    if (v.x > 0.0f) cand = lane * 4;
#pragma unroll
    for (int o = 16; o; o >>= 1) {
        int other = __shfl_xor_sync(0xFFFFFFFFu, cand, o);
        cand = (other < cand) ? other : cand;
    }
    int mi = cand;
    float w0 = 0.0f, w1 = 0.0f;
    if (mi < 128) {
        int e0 = mi & 3;
        float my0 = (e0 == 0) ? v.x : (e0 == 1) ? v.y : (e0 == 2) ? v.z : v.w;
        w0 = __shfl_sync(0xFFFFFFFFu, my0, mi >> 2);
        int m1 = mi + 1;
        if (m1 < 128) {
            int e1 = m1 & 3;
            float my1 = (e1 == 0) ? v.x : (e1 == 1) ? v.y : (e1 == 2) ? v.z : v.w;
            w1 = __shfl_sync(0xFFFFFFFFu, my1, m1 >> 2);
        }
    } else mi = 0;
    if (lane == 0) { g_mi[gw] = mi; g_w0[gw] = w0; g_w1[gw] = w1; }
}

// ---------------------------------------------------------------------------
// Prep 2 (single block): granule weight blocks + chunked warp-contained
// reduction schedule (<=3 chunks of 8 terms per mel, one chunk per lane).
// ---------------------------------------------------------------------------
__global__ void prep_sched() {
    __shared__ int s_mb[NGR];
    __shared__ unsigned char s_nzm[NGR];
    __shared__ int s_cnt[NM], s_start[NM], s_ccs[NM];
    const int t = threadIdx.x;

    {
        const int g = t;
        const int mb = g_mi[4 * g];
        float wv[4][4];
#pragma unroll
        for (int c = 0; c < 4; c++)
#pragma unroll
            for (int e = 0; e < 4; e++) wv[c][e] = 0.0f;
#pragma unroll
        for (int e = 0; e < 4; e++) {
            int f = 4 * g + e;
            int c0 = g_mi[f] - mb;
            if (c0 < 0) c0 = 0;
            if (c0 > 2) c0 = 2;
            wv[c0][e]     += g_w0[f];
            wv[c0 + 1][e] += g_w1[f];
        }
        unsigned char nz = 0;
#pragma unroll
        for (int c = 0; c < 4; c++) {
            float4 v = make_float4(wv[c][0], wv[c][1], wv[c][2], wv[c][3]);
            g_wv[g * 4 + c] = v;
            if (v.x != 0.0f || v.y != 0.0f || v.z != 0.0f || v.w != 0.0f)
                nz |= (unsigned char)(1u << c);
        }
        s_mb[g] = mb;
        s_nzm[g] = nz;
        g_mb[g] = mb;
    }
    __syncthreads();

    if (t < NM) {
        int n = 0;
        for (int g = 0; g < NGR; g++) {
            int c = t - s_mb[g];
            if (c >= 0 && c < 4 && ((s_nzm[g] >> c) & 1)) n++;
        }
        s_cnt[t] = n;
    }
    __syncthreads();

    if (t == 0) {
        int slot = 0;
        for (int m = 0; m < NM; m++) {
            int cc = (s_cnt[m] + 7) >> 3;
            if (cc < 1) cc = 1;
            if (cc > 3) cc = 3;
            if ((slot & 31) + cc > 32) slot = (slot + 31) & ~31;
            s_start[m] = slot; s_ccs[m] = cc; slot += cc;
        }
    }
    __syncthreads();

    g_sinfo[t] = 0xFFFFu;
#pragma unroll
    for (int j = 0; j < 8; j++) g_slist[t * 8 + j] = (unsigned short)DUMMYIDX;
    __syncthreads();

    if (t < NM) {
        int st = s_start[t], cc = s_ccs[t];
        g_sinfo[st] = (unsigned)t | ((unsigned)cc << 16);
        int n = 0;
        for (int g = 0; g < NGR; g++) {
            int c = t - s_mb[g];
            if (c >= 0 && c < 4 && ((s_nzm[g] >> c) & 1)) {
                if (n < cc * 8) g_slist[st * 8 + n] = (unsigned short)(c * NGR + g);
                n++;
            }
        }
    }
}

// ---------------------------------------------------------------------------
// Main: 20 SGD iterations, 8 rows/CTA (two f32x2 planes), occupancy 2.
// Doubles the independent work behind every barrier/LDS/shfl stall.
// ---------------------------------------------------------------------------
__global__ __launch_bounds__(NTHREADS, 2)
void invmel_main(const float* __restrict__ melspec,
                 const float* __restrict__ spec_init,
                 float* __restrict__ out) {
    __shared__ float4 s_p0[4 * NGR + 1];   // rows 0-3 partials (+zero dummy)
    __shared__ float4 s_p1[4 * NGR + 1];   // rows 4-7 partials (+zero dummy)
    __shared__ float4 s_d0[NDIFF];         // diff rows 0-3
    __shared__ float4 s_d1[NDIFF];         // diff rows 4-7
    __shared__ uint4  s_slist[NTHREADS];

    const float cINV = 2.0f / (float)(NB * TT);
    const int tid  = threadIdx.x;
    const int row0 = blockIdx.x * ROWS;
    const int b    = row0 / TT;
    const int t0   = row0 % TT;

    // scalar weights; packed on the fly (ALU pipe, hides in stall shadow)
    float wv[4][4];
#pragma unroll
    for (int c = 0; c < 4; c++) {
        float4 v = g_wv[tid * 4 + c];
        wv[c][0] = v.x; wv[c][1] = v.y; wv[c][2] = v.z; wv[c][3] = v.w;
    }
    const int mb = g_mb[tid];

    // packed state: sp[e][p], rb[e][p]; pair p = rows (2p, 2p+1)
    u64 sp[4][4], rb[4][4];
#pragma unroll
    for (int e = 0; e < 4; e++)
#pragma unroll
        for (int p = 0; p < 4; p++) {
            float va = spec_init[(size_t)(row0 + 2 * p)     * NF + 4 * tid + e];
            float vb = spec_init[(size_t)(row0 + 2 * p + 1) * NF + 4 * tid + e];
            PK2(sp[e][p], va, vb);
            rb[e][p] = 0ull;
        }
    u64 kMOM, kNINV, kNLR;
    PK2(kMOM, 0.9f, 0.9f);
    PK2(kNINV, -cINV, -cINV);
    PK2(kNLR, -0.3f, -0.3f);

    // reduction identity
    const unsigned sinfo = g_sinfo[tid];
    const int lmel = (int)(sinfo & 0xFFFFu);
    const int lcc  = (int)(sinfo >> 16);
    const float4* melp = (lmel < NM)
        ? (const float4*)&melspec[((size_t)b * NM + lmel) * TT + t0]
        : (const float4*)melspec;

    s_slist[tid] = ((const uint4*)g_slist)[tid];
    if (tid == 0) {
        s_p0[4 * NGR] = make_float4(0.f, 0.f, 0.f, 0.f);
        s_p1[4 * NGR] = make_float4(0.f, 0.f, 0.f, 0.f);
    }
    if (tid < NDIFF - NM) {
        s_d0[NM + tid] = make_float4(0.f, 0.f, 0.f, 0.f);
        s_d1[NM + tid] = make_float4(0.f, 0.f, 0.f, 0.f);
    }
    __syncthreads();

    for (int it = 0; it < ITERS; it++) {
        // ---- P1: per-granule channel partials, both planes ----
#pragma unroll
        for (int c = 0; c < 4; c++) {
            u64 wp, a0, a1, a2, a3;
            PK2(wp, wv[c][0], wv[c][0]);
            F2MUL(a0, wp, sp[0][0]);
            F2MUL(a1, wp, sp[0][1]);
            F2MUL(a2, wp, sp[0][2]);
            F2MUL(a3, wp, sp[0][3]);
#pragma unroll
            for (int e = 1; e < 4; e++) {
                PK2(wp, wv[c][e], wv[c][e]);
                F2FMA(a0, wp, sp[e][0], a0);
                F2FMA(a1, wp, sp[e][1], a1);
                F2FMA(a2, wp, sp[e][2], a2);
                F2FMA(a3, wp, sp[e][3], a3);
            }
            ulonglong2 v0; v0.x = a0; v0.y = a1;
            ulonglong2 v1; v1.x = a2; v1.y = a3;
            *(ulonglong2*)&s_p0[c * NGR + tid] = v0;
            *(ulonglong2*)&s_p1[c * NGR + tid] = v1;
        }
        __syncthreads();

        // ---- P2: uniform 8-term chunk sums, both planes ----
        const uint4 L = s_slist[tid];
        const int ix[8] = { (int)(L.x & 0xFFFF), (int)(L.x >> 16),
                            (int)(L.y & 0xFFFF), (int)(L.y >> 16),
                            (int)(L.z & 0xFFFF), (int)(L.z >> 16),
                            (int)(L.w & 0xFFFF), (int)(L.w >> 16) };
        ulonglong2 q0[8], q1[8];
#pragma unroll
        for (int j = 0; j < 8; j++) {
            q0[j] = *(const ulonglong2*)&s_p0[ix[j]];
            q1[j] = *(const ulonglong2*)&s_p1[ix[j]];
        }
        u64 A0, A1, A2, A3, tA, tB;
        // plane 0, pair 0 (rows 0,1)
        F2ADD(tA, q0[0].x, q0[1].x); F2ADD(tB, q0[2].x, q0[3].x); F2ADD(A0, tA, tB);
        F2ADD(tA, q0[4].x, q0[5].x); F2ADD(tB, q0[6].x, q0[7].x); F2ADD(tA, tA, tB);
        F2ADD(A0, A0, tA);
        // plane 0, pair 1 (rows 2,3)
        F2ADD(tA, q0[0].y, q0[1].y); F2ADD(tB, q0[2].y, q0[3].y); F2ADD(A1, tA, tB);
        F2ADD(tA, q0[4].y, q0[5].y); F2ADD(tB, q0[6].y, q0[7].y); F2ADD(tA, tA, tB);
        F2ADD(A1, A1, tA);
        // plane 1, pair 2 (rows 4,5)
        F2ADD(tA, q1[0].x, q1[1].x); F2ADD(tB, q1[2].x, q1[3].x); F2ADD(A2, tA, tB);
        F2ADD(tA, q1[4].x, q1[5].x); F2ADD(tB, q1[6].x, q1[7].x); F2ADD(tA, tA, tB);
        F2ADD(A2, A2, tA);
        // plane 1, pair 3 (rows 6,7)
        F2ADD(tA, q1[0].y, q1[1].y); F2ADD(tB, q1[2].y, q1[3].y); F2ADD(A3, tA, tB);
        F2ADD(tA, q1[4].y, q1[5].y); F2ADD(tB, q1[6].y, q1[7].y); F2ADD(tA, tA, tB);
        F2ADD(A3, A3, tA);

        // combine chunk partials across consecutive lanes (warp-contained)
        u64 s10 = __shfl_down_sync(0xFFFFFFFFu, A0, 1);
        u64 s11 = __shfl_down_sync(0xFFFFFFFFu, A1, 1);
        u64 s12 = __shfl_down_sync(0xFFFFFFFFu, A2, 1);
        u64 s13 = __shfl_down_sync(0xFFFFFFFFu, A3, 1);
        u64 s20 = __shfl_down_sync(0xFFFFFFFFu, A0, 2);
        u64 s21 = __shfl_down_sync(0xFFFFFFFFu, A1, 2);
        u64 s22 = __shfl_down_sync(0xFFFFFFFFu, A2, 2);
        u64 s23 = __shfl_down_sync(0xFFFFFFFFu, A3, 2);
        if (lmel < NM) {
            if (lcc >= 2) { F2ADD(A0, A0, s10); F2ADD(A1, A1, s11);
                            F2ADD(A2, A2, s12); F2ADD(A3, A3, s13); }
            if (lcc >= 3) { F2ADD(A0, A0, s20); F2ADD(A1, A1, s21);
                            F2ADD(A2, A2, s22); F2ADD(A3, A3, s23); }
            float e0, e1, e2, e3, e4, e5, e6, e7;
            UPK2(e0, e1, A0); UPK2(e2, e3, A1);
            UPK2(e4, e5, A2); UPK2(e6, e7, A3);
            float4 mv0 = __ldg(melp);      // t0..t0+3
            float4 mv1 = __ldg(melp + 1);  // t0+4..t0+7
            s_d0[lmel] = make_float4(mv0.x - e0, mv0.y - e1, mv0.z - e2, mv0.w - e3);
            s_d1[lmel] = make_float4(mv1.x - e4, mv1.y - e5, mv1.z - e6, mv1.w - e7);
        }
        __syncthreads();

        // ---- P3: grad + momentum + clamp, both planes ----
        ulonglong2 dA0 = *(const ulonglong2*)&s_d0[mb + 0];
        ulonglong2 dB0 = *(const ulonglong2*)&s_d0[mb + 1];
        ulonglong2 dC0 = *(const ulonglong2*)&s_d0[mb + 2];
        ulonglong2 dD0 = *(const ulonglong2*)&s_d0[mb + 3];
        ulonglong2 dA1 = *(const ulonglong2*)&s_d1[mb + 0];
        ulonglong2 dB1 = *(const ulonglong2*)&s_d1[mb + 1];
        ulonglong2 dC1 = *(const ulonglong2*)&s_d1[mb + 2];
        ulonglong2 dD1 = *(const ulonglong2*)&s_d1[mb + 3];
        const u64 dd[4][4] = { { dA0.x, dA0.y, dA1.x, dA1.y },
                               { dB0.x, dB0.y, dB1.x, dB1.y },
                               { dC0.x, dC0.y, dC1.x, dC1.y },
                               { dD0.x, dD0.y, dD1.x, dD1.y } };
#pragma unroll
        for (int e = 0; e < 4; e++) {
            u64 wp, g0, g1, g2, g3;
            PK2(wp, wv[0][e], wv[0][e]);
            F2MUL(g0, wp, dd[0][0]);
            F2MUL(g1, wp, dd[0][1]);
            F2MUL(g2, wp, dd[0][2]);
            F2MUL(g3, wp, dd[0][3]);
#pragma unroll
            for (int c = 1; c < 4; c++) {
                PK2(wp, wv[c][e], wv[c][e]);
                F2FMA(g0, wp, dd[c][0], g0);
                F2FMA(g1, wp, dd[c][1], g1);
                F2FMA(g2, wp, dd[c][2], g2);
                F2FMA(g3, wp, dd[c][3], g3);
            }
            u64 t0p, t1p, t2p, t3p;
            F2MUL(t0p, kNINV, g0);
            F2MUL(t1p, kNINV, g1);
            F2MUL(t2p, kNINV, g2);
            F2MUL(t3p, kNINV, g3);
            F2FMA(rb[e][0], kMOM, rb[e][0], t0p);
            F2FMA(rb[e][1], kMOM, rb[e][1], t1p);
            F2FMA(rb[e][2], kMOM, rb[e][2], t2p);
            F2FMA(rb[e][3], kMOM, rb[e][3], t3p);
#pragma unroll
            for (int p = 0; p < 4; p++) {
                u64 sv;
                F2FMA(sv, kNLR, rb[e][p], sp[e][p]);
                float lo, hi;
                UPK2(lo, hi, sv);
                PK2(sp[e][p], fmaxf(lo, 0.0f), fmaxf(hi, 0.0f));
            }
        }
        // no barrier: next P1 rewrites s_p* (read before last barrier);
        // s_d* rewritten only after the next iteration's first barrier.
    }

    // ---- output: 8 contiguous t per owned f = 2 STG.128 ----
#pragma unroll
    for (int e = 0; e < 4; e++) {
        ulonglong2 v0; v0.x = sp[e][0]; v0.y = sp[e][1];   // rows 0-3
        ulonglong2 v1; v1.x = sp[e][2]; v1.y = sp[e][3];   // rows 4-7
        ulonglong2* p = (ulonglong2*)&out[((size_t)b * NF + 4 * tid + e) * TT + t0];
        p[0] = v0;
        p[1] = v1;
    }
    if (tid < ROWS) {   // f = 1024: zero fb row -> passthrough
        out[((size_t)b * NF + 1024) * TT + t0 + tid] =
            spec_init[(size_t)(row0 + tid) * NF + 1024];
    }
}

// ---------------------------------------------------------------------------
extern "C" void kernel_launch(void* const* d_in, const int* in_sizes, int n_in,
                              void* d_out, int out_size) {
    const float* melspec = nullptr;
    const float* spec_init = nullptr;
    const float* fb = nullptr;
    for (int i = 0; i < n_in; i++) {
        if (in_sizes[i] == NB * NM * TT)      melspec   = (const float*)d_in[i];
        else if (in_sizes[i] == NB * TT * NF) spec_init = (const float*)d_in[i];
        else if (in_sizes[i] == NF * NM)      fb        = (const float*)d_in[i];
    }
    float* out = (float*)d_out;

    prep_freq<<<(NF * 32 + 255) / 256, 256>>>(fb);
    prep_sched<<<1, NTHREADS>>>();
    invmel_main<<<NBLOCKS, NTHREADS>>>(melspec, spec_init, out);
}